// round 9
// baseline (speedup 1.0000x reference)
#include <cuda_runtime.h>

// CharRNN: 3-layer tanh RNN, B=512, T=1024, HID=100, VOCAB=62.
// R9: R8 structure with the two measured defects fixed:
//     (1) 8 warps / 256 thr -> balanced 2 warps per SMSP (R8's 7 warps left
//         SMSP3 with a lone warp pacing every barrier);
//     (2) token + table LDGs pipelined ahead of the dot (L1D is only ~18KB
//         with 209KB smem carveout, so table hits L2 ~250cyc — must overlap).
//     13 j-slots/warp (jA=wid*13+j2, jB=wid*13+8+j2 for j2<5, clamped).
//     Decoder stays offloaded; persistent dec kernel stages W_dec once.

#define BB    512
#define TT    1024
#define HID   100
#define VOCAB 62
#define NL    3
#define ROWS  4
#define NCTA  (BB / ROWS)       // 128
#define NTHR  256               // 8 warps, 2 per SMSP

// ---- rnn shared memory layout (floats) ----
#define OFF_WH1  0
#define OFF_WI2  10000
#define OFF_WH2  20000
#define OFF_WI3  30000
#define OFF_WH3  40000
#define OFF_H    50000          // [2 buf][NL][ROWS][HID] = 2*1200
#define SMEM_FLOATS (OFF_H + 2 * NL * ROWS * HID)   // 52,400 -> 209,600 B

typedef unsigned long long ull;

__device__ float g_table[VOCAB * HID];                  // emb@Wi1^T + b1
__device__ float g_h3[(size_t)BB * TT * HID];           // h3 stream (200 MB)

// ---------------------------------------------------------------------------
__global__ void table_kernel(const float* __restrict__ emb,
                             const float* __restrict__ W_ih,
                             const float* __restrict__ b_ih,
                             const float* __restrict__ b_hh) {
    int v = blockIdx.x;
    int j = threadIdx.x;
    if (j >= HID) return;
    float acc = b_ih[j] + b_hh[j];
    const float* e = emb + v * HID;
    const float* w = W_ih + j * HID;
#pragma unroll
    for (int k = 0; k < HID; k++) acc += e[k] * w[k];
    g_table[v * HID + j] = acc;
}

// ---------------------------------------------------------------------------
__device__ __forceinline__ void fma2(ull& acc, ull a, ull b) {
    asm("fma.rn.f32x2 %0, %1, %2, %3;" : "=l"(acc) : "l"(a), "l"(b), "l"(acc));
}
__device__ __forceinline__ float hadd2(ull a) {
    float lo = __uint_as_float((unsigned)a);
    float hi = __uint_as_float((unsigned)(a >> 32));
    return lo + hi;
}
__device__ __forceinline__ ulonglong2 ldv(const float* pf) {
    return *reinterpret_cast<const ulonglong2*>(pf);
}
__device__ __forceinline__ float tanho(float x) {
    float e = __expf(2.0f * x);
    return 1.0f - __fdividef(2.0f, e + 1.0f);
}

// ---------------------------------------------------------------------------
__global__ __launch_bounds__(NTHR, 1)
void rnn_kernel(const int*   __restrict__ ids,
                const float* __restrict__ W_ih,
                const float* __restrict__ W_hh,
                const float* __restrict__ b_ih,
                const float* __restrict__ b_hh,
                float* __restrict__ hidden) {
    extern __shared__ float s[];
    const int tid  = threadIdx.x;
    const int wid  = tid >> 5;
    const int lane = tid & 31;
    const int row  = lane >> 3;           // 0..3 batch row
    const int j2   = lane & 7;            // 0..7
    const int b0   = blockIdx.x * ROWS;

    // 13 j-slots per warp: jA = wid*13 + j2 (j2 0..7), jB = wid*13+8+j2 (j2 0..4)
    const int jA  = wid * 13 + j2;
    const int jB  = wid * 13 + 8 + j2;
    const int jAc = (jA < HID) ? jA : (HID - 1);
    const int jBc = (jB < HID) ? jB : (HID - 1);
    const bool wA = (jA < HID);
    const bool wB = (j2 < 5) && (jB < HID);
    const int oA = jAc * HID;
    const int oB = jBc * HID;

    // ---- stage weights ----
    for (int i = tid; i < HID * HID; i += NTHR) {
        s[OFF_WH1 + i] = W_hh[i];
        s[OFF_WI2 + i] = W_ih[1 * HID * HID + i];
        s[OFF_WH2 + i] = W_hh[1 * HID * HID + i];
        s[OFF_WI3 + i] = W_ih[2 * HID * HID + i];
        s[OFF_WH3 + i] = W_hh[2 * HID * HID + i];
    }
    for (int i = tid; i < 2 * NL * ROWS * HID; i += NTHR) s[OFF_H + i] = 0.0f;

    const float b2A = b_ih[1 * HID + jAc] + b_hh[1 * HID + jAc];
    const float b2B = b_ih[1 * HID + jBc] + b_hh[1 * HID + jBc];
    const float b3A = b_ih[2 * HID + jAc] + b_hh[2 * HID + jAc];
    const float b3B = b_ih[2 * HID + jBc] + b_hh[2 * HID + jBc];
    __syncthreads();

    // ---- pre-loop: h1(0) = tanh(table[tok0]); prefetch tok(1) ----
    {
        int tk0 = ids[(b0 + row) * TT];
        float* h1n = s + OFF_H;           // buf0, layer0
        if (wA) h1n[row * HID + jA] = tanho(g_table[tk0 * HID + jAc]);
        if (wB) h1n[row * HID + jB] = tanho(g_table[tk0 * HID + jBc]);
    }
    int tknext = ids[(b0 + row) * TT + 1];   // token for step u+1 (u=0)
    __syncthreads();

    for (int u = 0; u < TT; u++) {
        const int bu = (u & 1) * 1200, bo = 1200 - bu;

        // ========= P1: L2(u) + L1(u+1) =========
        {
            const float* h1u = s + OFF_H + bu + 0   + row * HID;   // h1(u)
            const float* h2p = s + OFF_H + bo + 400 + row * HID;   // h2(u-1)
            float* h2n = s + OFF_H + bu + 400;                     // h2(u)
            float* h1n = s + OFF_H + bo + 0;                       // h1(u+1)

            // issue table LDGs FIRST so L2 latency overlaps the dot below
            const float tA = g_table[tknext * HID + jAc];
            const float tB = g_table[tknext * HID + jBc];

            ull a2A = 0, a2B = 0, a1A = 0, a1B = 0;
#pragma unroll
            for (int kc = 0; kc < 25; kc++) {
                ulonglong2 h1q = ldv(h1u + 4 * kc);
                ulonglong2 h2q = ldv(h2p + 4 * kc);
                ulonglong2 wiA = ldv(s + OFF_WI2 + oA + 4 * kc);
                ulonglong2 whA = ldv(s + OFF_WH2 + oA + 4 * kc);
                ulonglong2 wiB = ldv(s + OFF_WI2 + oB + 4 * kc);
                ulonglong2 whB = ldv(s + OFF_WH2 + oB + 4 * kc);
                ulonglong2 w1A = ldv(s + OFF_WH1 + oA + 4 * kc);
                ulonglong2 w1B = ldv(s + OFF_WH1 + oB + 4 * kc);
                fma2(a2A, wiA.x, h1q.x); fma2(a2A, wiA.y, h1q.y);
                fma2(a2A, whA.x, h2q.x); fma2(a2A, whA.y, h2q.y);
                fma2(a2B, wiB.x, h1q.x); fma2(a2B, wiB.y, h1q.y);
                fma2(a2B, whB.x, h2q.x); fma2(a2B, whB.y, h2q.y);
                fma2(a1A, w1A.x, h1q.x); fma2(a1A, w1A.y, h1q.y);
                fma2(a1B, w1B.x, h1q.x); fma2(a1B, w1B.y, h1q.y);
            }
            if (wA) h2n[row * HID + jA] = tanho(b2A + hadd2(a2A));
            if (wB) h2n[row * HID + jB] = tanho(b2B + hadd2(a2B));
            if (u + 1 < TT) {
                if (wA) h1n[row * HID + jA] = tanho(tA + hadd2(a1A));
                if (wB) h1n[row * HID + jB] = tanho(tB + hadd2(a1B));
            }
        }
        __syncthreads();

        // ========= P2: L3(u) + h3 stream-out + tok prefetch =========
        {
            const float* h2c = s + OFF_H + bu + 400 + row * HID;   // h2(u)
            const float* h3p = s + OFF_H + bo + 800 + row * HID;   // h3(u-1)
            float* h3n = s + OFF_H + bu + 800;                     // h3(u)

            // prefetch token for step u+2 (consumed by P1 of u+1)
            const int tn = (u + 2 < TT) ? (u + 2) : (TT - 1);
            tknext = ids[(b0 + row) * TT + tn];

            ull a3A = 0, a3B = 0;
#pragma unroll
            for (int kc = 0; kc < 25; kc++) {
                ulonglong2 h2q = ldv(h2c + 4 * kc);
                ulonglong2 h3q = ldv(h3p + 4 * kc);
                ulonglong2 wiA = ldv(s + OFF_WI3 + oA + 4 * kc);
                ulonglong2 whA = ldv(s + OFF_WH3 + oA + 4 * kc);
                ulonglong2 wiB = ldv(s + OFF_WI3 + oB + 4 * kc);
                ulonglong2 whB = ldv(s + OFF_WH3 + oB + 4 * kc);
                fma2(a3A, wiA.x, h2q.x); fma2(a3A, wiA.y, h2q.y);
                fma2(a3A, whA.x, h3q.x); fma2(a3A, whA.y, h3q.y);
                fma2(a3B, wiB.x, h2q.x); fma2(a3B, wiB.y, h2q.y);
                fma2(a3B, whB.x, h3q.x); fma2(a3B, whB.y, h3q.y);
            }
            float* g = g_h3 + ((size_t)(b0 + row) * TT + u) * HID;
            if (wA) {
                float v = tanho(b3A + hadd2(a3A));
                h3n[row * HID + jA] = v;
                g[jA] = v;
            }
            if (wB) {
                float v = tanho(b3B + hadd2(a3B));
                h3n[row * HID + jB] = v;
                g[jB] = v;
            }
        }
        __syncthreads();
    }

    // ---- final hidden [NL, B, HID]: all final states in buf 1 ----
    for (int i = tid; i < NL * ROWS * HID; i += NTHR) {
        const int l = i / (ROWS * HID);
        const int rem = i - l * (ROWS * HID);
        const int r = rem / HID;
        const int j = rem - r * HID;
        hidden[(size_t)(l * BB + b0 + r) * HID + j] = s[OFF_H + 1200 + i];
    }
}

// ---------------------------------------------------------------------------
// Decoder GEMM (persistent): logits[bt][v] = b_dec[v] + h3[bt] . W_dec[v]
// 128 CTAs x 32 tiles of 128 rows; W_dec staged to smem ONCE per CTA.
// ---------------------------------------------------------------------------
#define DT     256
#define GR     128
#define NDC    128
#define DTILES ((BB * TT) / GR / NDC)    // 32
#define DS_W   0                         // 6200 floats
#define DS_H   6208                      // 12800 floats (16B aligned)
#define DS_B   19008                     // 62 floats
#define DS_FLOATS 19072                  // 76,288 B

__global__ __launch_bounds__(DT, 1)
void dec_kernel(const float* __restrict__ W_dec,
                const float* __restrict__ b_dec,
                float* __restrict__ logits) {
    extern __shared__ float ds[];
    const int tid = threadIdx.x;

    float4* sw4 = reinterpret_cast<float4*>(ds + DS_W);
    const float4* wsrc = reinterpret_cast<const float4*>(W_dec);
    for (int i = tid; i < VOCAB * HID / 4; i += DT) sw4[i] = wsrc[i];
    for (int i = tid; i < VOCAB; i += DT) ds[DS_B + i] = b_dec[i];

    const int r    = tid & 127;
    const int half = tid >> 7;
    const int jb   = half * 31;
    const float* hrow = ds + DS_H + r * HID;

    for (int it = 0; it < DTILES; it++) {
        const int tile = blockIdx.x * DTILES + it;

        __syncthreads();   // protect ds H region from previous iteration's readers
        float4* sh4 = reinterpret_cast<float4*>(ds + DS_H);
        const float4* hsrc =
            reinterpret_cast<const float4*>(g_h3 + (size_t)tile * GR * HID);
        for (int i = tid; i < GR * HID / 4; i += DT) sh4[i] = hsrc[i];
        __syncthreads();

        ull acc[31];
#pragma unroll
        for (int jj = 0; jj < 31; jj++) acc[jj] = 0ull;

        for (int kc = 0; kc < 25; kc++) {
            ulonglong2 hq = ldv(hrow + 4 * kc);
#pragma unroll
            for (int jj = 0; jj < 31; jj++) {
                ulonglong2 wq = ldv(ds + DS_W + (jb + jj) * HID + 4 * kc);
                fma2(acc[jj], wq.x, hq.x);
                fma2(acc[jj], wq.y, hq.y);
            }
        }

        float* out = logits + ((size_t)tile * GR + r) * VOCAB + jb;
#pragma unroll
        for (int jj = 0; jj < 31; jj++)
            out[jj] = ds[DS_B + jb + jj] + hadd2(acc[jj]);
    }
}

// ---------------------------------------------------------------------------
extern "C" void kernel_launch(void* const* d_in, const int* in_sizes, int n_in,
                              void* d_out, int out_size) {
    const int*   ids   = (const int*)  d_in[0];
    const float* emb   = (const float*)d_in[1];
    const float* W_ih  = (const float*)d_in[2];
    const float* W_hh  = (const float*)d_in[3];
    const float* b_ih  = (const float*)d_in[4];
    const float* b_hh  = (const float*)d_in[5];
    const float* W_dec = (const float*)d_in[6];
    const float* b_dec = (const float*)d_in[7];

    float* out    = (float*)d_out;
    float* logits = out;
    float* hidden = out + ((size_t)out_size - (size_t)NL * BB * HID);

    table_kernel<<<VOCAB, 128>>>(emb, W_ih, b_ih, b_hh);

    size_t smem = SMEM_FLOATS * sizeof(float);
    cudaFuncSetAttribute(rnn_kernel, cudaFuncAttributeMaxDynamicSharedMemorySize,
                         (int)smem);
    rnn_kernel<<<NCTA, NTHR, smem>>>(ids, W_ih, W_hh, b_ih, b_hh, hidden);

    size_t dsmem = DS_FLOATS * sizeof(float);
    cudaFuncSetAttribute(dec_kernel, cudaFuncAttributeMaxDynamicSharedMemorySize,
                         (int)dsmem);
    dec_kernel<<<NDC, DT, dsmem>>>(W_dec, b_dec, logits);
}

// round 10
// speedup vs baseline: 1.4031x; 1.4031x over previous
#include <cuda_runtime.h>

// CharRNN: 3-layer tanh RNN, B=512, T=1024, HID=100, VOCAB=62.
// R10: R3 (the 4116us champion) with exactly three proven fixes:
//   1. decoder phase removed from the recurrence -> h3 streamed to gmem,
//      separate dec GEMM kernel (R8-validated). 8 -> 6 barriers/step.
//   2. tanhf -> tanho (__expf-based, ~6 instr; accuracy proven 5e-7).
//   3. token prefetched one step ahead (kills serial ids->table L2 chain).
// Everything else identical to R3: 256 thr, cross-warp 2-way k-split with
// smem scratch reduction, float4 broadcast loads, in-place h update.

#define BB    512
#define TT    1024
#define HID   100
#define VOCAB 62
#define NL    3
#define ROWS  4
#define NCTA  (BB / ROWS)       // 128
#define NTHR  256

// ---- shared memory layout (floats) ----
#define OFF_WH1  0              // 100x100
#define OFF_WI2  10000
#define OFF_WH2  20000
#define OFF_WI3  30000
#define OFF_WH3  40000
#define OFF_SCR  50000          // 128 j * 4 floats (reduction scratch)
#define OFF_H1   50512          // 4x100
#define OFF_H2   50912
#define OFF_H3   51312
#define SMEM_FLOATS 51712       // 206,848 bytes

typedef unsigned long long ull;

__device__ float g_table[VOCAB * HID];            // emb@Wi1^T + b_ih1 + b_hh1
__device__ float g_h3[(size_t)BB * TT * HID];     // h3 stream (200 MB)

// ---------------------------------------------------------------------------
__global__ void table_kernel(const float* __restrict__ emb,
                             const float* __restrict__ W_ih,
                             const float* __restrict__ b_ih,
                             const float* __restrict__ b_hh) {
    int v = blockIdx.x;
    int j = threadIdx.x;
    if (j >= HID) return;
    float acc = b_ih[j] + b_hh[j];
    const float* e = emb + v * HID;
    const float* w = W_ih + j * HID;
#pragma unroll
    for (int k = 0; k < HID; k++) acc += e[k] * w[k];
    g_table[v * HID + j] = acc;
}

// ---------------------------------------------------------------------------
__device__ __forceinline__ void fma2(ull& acc, ull a, ull b) {
    asm("fma.rn.f32x2 %0, %1, %2, %3;" : "=l"(acc) : "l"(a), "l"(b), "l"(acc));
}
__device__ __forceinline__ float hadd2(ull a) {
    float lo = __uint_as_float((unsigned)a);
    float hi = __uint_as_float((unsigned)(a >> 32));
    return lo + hi;
}
__device__ __forceinline__ float tanho(float x) {
    float e = __expf(2.0f * x);
    return 1.0f - __fdividef(2.0f, e + 1.0f);
}

// partial dot over chunks [KB,KE): acc[r] += w_row . h_row_r  (packed f32x2)
template <int KB, int KE>
__device__ __forceinline__ void dot1(const float* __restrict__ wrow,
                                     const float* __restrict__ hbase,
                                     ull acc[ROWS]) {
#pragma unroll
    for (int kc = KB; kc < KE; kc++) {
        ulonglong2 w = *reinterpret_cast<const ulonglong2*>(wrow + kc * 4);
#pragma unroll
        for (int r = 0; r < ROWS; r++) {
            ulonglong2 h = *reinterpret_cast<const ulonglong2*>(hbase + r * HID + kc * 4);
            fma2(acc[r], w.x, h.x);
            fma2(acc[r], w.y, h.y);
        }
    }
}

// two-matrix partial dot: acc[r] += wa . ha_r + wb . hb_r
template <int KB, int KE>
__device__ __forceinline__ void dot2(const float* __restrict__ warow,
                                     const float* __restrict__ wbrow,
                                     const float* __restrict__ habase,
                                     const float* __restrict__ hbbase,
                                     ull acc[ROWS]) {
#pragma unroll
    for (int kc = KB; kc < KE; kc++) {
        ulonglong2 wa = *reinterpret_cast<const ulonglong2*>(warow + kc * 4);
        ulonglong2 wb = *reinterpret_cast<const ulonglong2*>(wbrow + kc * 4);
#pragma unroll
        for (int r = 0; r < ROWS; r++) {
            ulonglong2 ha = *reinterpret_cast<const ulonglong2*>(habase + r * HID + kc * 4);
            ulonglong2 hb = *reinterpret_cast<const ulonglong2*>(hbbase + r * HID + kc * 4);
            fma2(acc[r], wa.x, ha.x);
            fma2(acc[r], wa.y, ha.y);
            fma2(acc[r], wb.x, hb.x);
            fma2(acc[r], wb.y, hb.y);
        }
    }
}

// ---------------------------------------------------------------------------
__global__ __launch_bounds__(NTHR, 1)
void rnn_kernel(const int*   __restrict__ ids,
                const float* __restrict__ W_ih,
                const float* __restrict__ W_hh,
                const float* __restrict__ b_ih,
                const float* __restrict__ b_hh,
                float* __restrict__ hidden) {
    extern __shared__ float s[];
    const int tid = threadIdx.x;
    const int p   = tid >> 7;       // k-split group: 0 or 1
    const int j   = tid & 127;      // neuron index
    const int b0  = blockIdx.x * ROWS;

    // ---- stage weights into smem ----
    for (int i = tid; i < HID * HID; i += NTHR) {
        s[OFF_WH1 + i] = W_hh[i];
        s[OFF_WI2 + i] = W_ih[1 * HID * HID + i];
        s[OFF_WH2 + i] = W_hh[1 * HID * HID + i];
        s[OFF_WI3 + i] = W_ih[2 * HID * HID + i];
        s[OFF_WH3 + i] = W_hh[2 * HID * HID + i];
    }
    for (int i = tid; i < ROWS * HID; i += NTHR) {
        s[OFF_H1 + i] = 0.0f;
        s[OFF_H2 + i] = 0.0f;
        s[OFF_H3 + i] = 0.0f;
    }
    // biases -> registers (only the reducer group p==0 needs them)
    float rb2 = 0.f, rb3 = 0.f;
    if (p == 0 && j < HID) {
        rb2 = b_ih[1 * HID + j] + b_hh[1 * HID + j];
        rb3 = b_ih[2 * HID + j] + b_hh[2 * HID + j];
    }
    __syncthreads();

    const float* wh1 = s + OFF_WH1 + j * HID;
    const float* wi2 = s + OFF_WI2 + j * HID;
    const float* wh2 = s + OFF_WH2 + j * HID;
    const float* wi3 = s + OFF_WI3 + j * HID;
    const float* wh3 = s + OFF_WH3 + j * HID;

    // token prefetch (one step ahead)
    int tok[ROWS];
#pragma unroll
    for (int r = 0; r < ROWS; r++) tok[r] = ids[(b0 + r) * TT];

    for (int t = 0; t < TT; t++) {
        // ---- layer-1 token-table inputs (reducer group only; tok already
        //      in registers, so the table LDG issues immediately and hides
        //      under the dot below) ----
        float tbl[ROWS];
        if (p == 0 && j < HID) {
#pragma unroll
            for (int r = 0; r < ROWS; r++) tbl[r] = g_table[tok[r] * HID + j];
        }

        // ================= layer 1 =================
        {
            ull acc[ROWS] = {0ull, 0ull, 0ull, 0ull};
            if (j < HID) {
                if (p == 0) dot1<0, 13>(wh1, s + OFF_H1, acc);
                else        dot1<13, 25>(wh1, s + OFF_H1, acc);
            }
            float4 part;
            part.x = hadd2(acc[0]); part.y = hadd2(acc[1]);
            part.z = hadd2(acc[2]); part.w = hadd2(acc[3]);
            if (p == 1 && j < HID)
                *reinterpret_cast<float4*>(&s[OFF_SCR + 4 * j]) = part;
            __syncthreads();
            if (p == 0 && j < HID) {
                float4 o = *reinterpret_cast<const float4*>(&s[OFF_SCR + 4 * j]);
                s[OFF_H1 + 0 * HID + j] = tanho(tbl[0] + part.x + o.x);
                s[OFF_H1 + 1 * HID + j] = tanho(tbl[1] + part.y + o.y);
                s[OFF_H1 + 2 * HID + j] = tanho(tbl[2] + part.z + o.z);
                s[OFF_H1 + 3 * HID + j] = tanho(tbl[3] + part.w + o.w);
            }
            __syncthreads();
        }

        // ================= layer 2 =================
        {
            ull acc[ROWS] = {0ull, 0ull, 0ull, 0ull};
            if (j < HID) {
                if (p == 0) dot2<0, 13>(wi2, wh2, s + OFF_H1, s + OFF_H2, acc);
                else        dot2<13, 25>(wi2, wh2, s + OFF_H1, s + OFF_H2, acc);
            }
            float4 part;
            part.x = hadd2(acc[0]); part.y = hadd2(acc[1]);
            part.z = hadd2(acc[2]); part.w = hadd2(acc[3]);
            if (p == 1 && j < HID)
                *reinterpret_cast<float4*>(&s[OFF_SCR + 4 * j]) = part;
            __syncthreads();
            if (p == 0 && j < HID) {
                float4 o = *reinterpret_cast<const float4*>(&s[OFF_SCR + 4 * j]);
                s[OFF_H2 + 0 * HID + j] = tanho(rb2 + part.x + o.x);
                s[OFF_H2 + 1 * HID + j] = tanho(rb2 + part.y + o.y);
                s[OFF_H2 + 2 * HID + j] = tanho(rb2 + part.z + o.z);
                s[OFF_H2 + 3 * HID + j] = tanho(rb2 + part.w + o.w);
            }
            __syncthreads();
        }

        // ================= layer 3 (+ h3 stream-out, + tok prefetch) ======
        {
            // prefetch next step's tokens (consumed next iteration)
            const int tn = (t + 1 < TT) ? (t + 1) : (TT - 1);
#pragma unroll
            for (int r = 0; r < ROWS; r++) tok[r] = ids[(b0 + r) * TT + tn];

            ull acc[ROWS] = {0ull, 0ull, 0ull, 0ull};
            if (j < HID) {
                if (p == 0) dot2<0, 13>(wi3, wh3, s + OFF_H2, s + OFF_H3, acc);
                else        dot2<13, 25>(wi3, wh3, s + OFF_H2, s + OFF_H3, acc);
            }
            float4 part;
            part.x = hadd2(acc[0]); part.y = hadd2(acc[1]);
            part.z = hadd2(acc[2]); part.w = hadd2(acc[3]);
            if (p == 1 && j < HID)
                *reinterpret_cast<float4*>(&s[OFF_SCR + 4 * j]) = part;
            __syncthreads();
            if (p == 0 && j < HID) {
                float4 o = *reinterpret_cast<const float4*>(&s[OFF_SCR + 4 * j]);
                float v0 = tanho(rb3 + part.x + o.x);
                float v1 = tanho(rb3 + part.y + o.y);
                float v2 = tanho(rb3 + part.z + o.z);
                float v3 = tanho(rb3 + part.w + o.w);
                s[OFF_H3 + 0 * HID + j] = v0;
                s[OFF_H3 + 1 * HID + j] = v1;
                s[OFF_H3 + 2 * HID + j] = v2;
                s[OFF_H3 + 3 * HID + j] = v3;
                // coalesced stream-out (consecutive j within warp)
                g_h3[((size_t)(b0 + 0) * TT + t) * HID + j] = v0;
                g_h3[((size_t)(b0 + 1) * TT + t) * HID + j] = v1;
                g_h3[((size_t)(b0 + 2) * TT + t) * HID + j] = v2;
                g_h3[((size_t)(b0 + 3) * TT + t) * HID + j] = v3;
            }
            __syncthreads();
        }
    }

    // ---- final hidden states: [NL, B, HID] ----
    if (p == 0 && j < HID) {
#pragma unroll
        for (int r = 0; r < ROWS; r++) {
            hidden[(size_t)(0 * BB + b0 + r) * HID + j] = s[OFF_H1 + r * HID + j];
            hidden[(size_t)(1 * BB + b0 + r) * HID + j] = s[OFF_H2 + r * HID + j];
            hidden[(size_t)(2 * BB + b0 + r) * HID + j] = s[OFF_H3 + r * HID + j];
        }
    }
}

// ---------------------------------------------------------------------------
// Decoder GEMM (R8-validated): logits[bt][v] = b_dec[v] + h3[bt] . W_dec[v]
// ---------------------------------------------------------------------------
#define DT   256
#define GR   128
#define DS_W 0                       // 6200 floats
#define DS_H 6208                    // 12800 floats (16B aligned)
#define DS_B 19008                   // 62 floats
#define DS_FLOATS 19072              // 76,288 B

__global__ __launch_bounds__(DT)
void dec_kernel(const float* __restrict__ W_dec,
                const float* __restrict__ b_dec,
                float* __restrict__ logits) {
    extern __shared__ float ds[];
    const int tid  = threadIdx.x;
    const int tile = blockIdx.x;

    float4* sw4 = reinterpret_cast<float4*>(ds + DS_W);
    const float4* wsrc = reinterpret_cast<const float4*>(W_dec);
    for (int i = tid; i < VOCAB * HID / 4; i += DT) sw4[i] = wsrc[i];

    float4* sh4 = reinterpret_cast<float4*>(ds + DS_H);
    const float4* hsrc = reinterpret_cast<const float4*>(g_h3 + (size_t)tile * GR * HID);
    for (int i = tid; i < GR * HID / 4; i += DT) sh4[i] = hsrc[i];

    for (int i = tid; i < VOCAB; i += DT) ds[DS_B + i] = b_dec[i];
    __syncthreads();

    const int r    = tid & 127;
    const int half = tid >> 7;
    const int jb   = half * 31;

    ull acc[31];
#pragma unroll
    for (int jj = 0; jj < 31; jj++) acc[jj] = 0ull;

    const float* hrow = ds + DS_H + r * HID;
    for (int kc = 0; kc < 25; kc++) {
        ulonglong2 hq = *reinterpret_cast<const ulonglong2*>(hrow + 4 * kc);
#pragma unroll
        for (int jj = 0; jj < 31; jj++) {
            ulonglong2 wq = *reinterpret_cast<const ulonglong2*>(ds + DS_W + (jb + jj) * HID + 4 * kc);
            fma2(acc[jj], wq.x, hq.x);
            fma2(acc[jj], wq.y, hq.y);
        }
    }

    float* out = logits + ((size_t)tile * GR + r) * VOCAB + jb;
#pragma unroll
    for (int jj = 0; jj < 31; jj++)
        out[jj] = ds[DS_B + jb + jj] + hadd2(acc[jj]);
}

// ---------------------------------------------------------------------------
extern "C" void kernel_launch(void* const* d_in, const int* in_sizes, int n_in,
                              void* d_out, int out_size) {
    const int*   ids   = (const int*)  d_in[0];
    const float* emb   = (const float*)d_in[1];
    const float* W_ih  = (const float*)d_in[2];
    const float* W_hh  = (const float*)d_in[3];
    const float* b_ih  = (const float*)d_in[4];
    const float* b_hh  = (const float*)d_in[5];
    const float* W_dec = (const float*)d_in[6];
    const float* b_dec = (const float*)d_in[7];

    float* out    = (float*)d_out;
    float* logits = out;
    float* hidden = out + ((size_t)out_size - (size_t)NL * BB * HID);

    table_kernel<<<VOCAB, 128>>>(emb, W_ih, b_ih, b_hh);

    size_t smem = SMEM_FLOATS * sizeof(float);
    cudaFuncSetAttribute(rnn_kernel, cudaFuncAttributeMaxDynamicSharedMemorySize,
                         (int)smem);
    rnn_kernel<<<NCTA, NTHR, smem>>>(ids, W_ih, W_hh, b_ih, b_hh, hidden);

    size_t dsmem = DS_FLOATS * sizeof(float);
    cudaFuncSetAttribute(dec_kernel, cudaFuncAttributeMaxDynamicSharedMemorySize,
                         (int)dsmem);
    dec_kernel<<<(BB * TT) / GR, DT, dsmem>>>(W_dec, b_dec, logits);
}